// round 2
// baseline (speedup 1.0000x reference)
#include <cuda_runtime.h>

// Problem constants (from reference): P=50000, H=W=28, CARD=50
// Inputs (metadata order): p[50000] f32, I[784*50000] f32, J[784*50000] f32,
//                          inds1[100*2] i32, inds2[100*2] i32
// Output: 200 f32 (dgm1 flat [100] then dgm2 flat [100])

#define P_DIM   50000
#define W_IMG   28
#define N_OUT   200
#define SPLIT   4
#define CHUNK   (P_DIM / SPLIT)     // 12500
#define CHUNK4  (CHUNK / 4)         // 3125 float4 per chunk
#define NTHREADS 256

__device__ float g_partial[N_OUT * SPLIT];

__global__ __launch_bounds__(NTHREADS)
void gathered_dot_kernel(const float* __restrict__ p,
                         const float* __restrict__ I,
                         const float* __restrict__ J,
                         const int*   __restrict__ inds1,
                         const int*   __restrict__ inds2) {
    int b = blockIdx.x;          // 0 .. N_OUT*SPLIT-1
    int o = b >> 2;              // output index 0..199
    int c = b & (SPLIT - 1);     // K-chunk 0..3

    const float* mat;
    const int*   inds;
    int j;
    if (o < 100) { mat = I; inds = inds1; j = o; }
    else         { mat = J; inds = inds2; j = o - 100; }

    int r  = inds[2 * j + 0];
    int cc = inds[2 * j + 1];
    const float* row = mat + (size_t)(r * W_IMG + cc) * P_DIM + c * CHUNK;
    const float* pp  = p + c * CHUNK;

    const float4* row4 = reinterpret_cast<const float4*>(row);
    const float4* p4   = reinterpret_cast<const float4*>(pp);

    float sum = 0.0f;
    #pragma unroll 4
    for (int i = threadIdx.x; i < CHUNK4; i += NTHREADS) {
        float4 a = row4[i];
        float4 q = p4[i];
        sum += a.x * q.x + a.y * q.y + a.z * q.z + a.w * q.w;
    }

    // warp reduction
    #pragma unroll
    for (int off = 16; off > 0; off >>= 1)
        sum += __shfl_down_sync(0xffffffffu, sum, off);

    __shared__ float ws[NTHREADS / 32];
    if ((threadIdx.x & 31) == 0) ws[threadIdx.x >> 5] = sum;
    __syncthreads();

    if (threadIdx.x < (NTHREADS / 32)) {
        float v = ws[threadIdx.x];
        #pragma unroll
        for (int off = (NTHREADS / 64); off > 0; off >>= 1)
            v += __shfl_down_sync(0xffu, v, off);
        if (threadIdx.x == 0) g_partial[o * SPLIT + c] = v;
    }
}

__global__ void reduce_kernel(float* __restrict__ out) {
    int o = blockIdx.x * blockDim.x + threadIdx.x;
    if (o < N_OUT) {
        float s = 0.0f;
        #pragma unroll
        for (int c = 0; c < SPLIT; c++) s += g_partial[o * SPLIT + c];
        out[o] = s;
    }
}

extern "C" void kernel_launch(void* const* d_in, const int* in_sizes, int n_in,
                              void* d_out, int out_size) {
    const float* p     = (const float*)d_in[0];
    const float* I     = (const float*)d_in[1];
    const float* J     = (const float*)d_in[2];
    const int*   inds1 = (const int*)d_in[3];
    const int*   inds2 = (const int*)d_in[4];
    float* out = (float*)d_out;

    gathered_dot_kernel<<<N_OUT * SPLIT, NTHREADS>>>(p, I, J, inds1, inds2);
    reduce_kernel<<<1, N_OUT>>>(out);
}

// round 3
// speedup vs baseline: 1.1860x; 1.1860x over previous
#include <cuda_runtime.h>

// Problem constants: P=50000, H=W=28, CARD=50
// Inputs: p[50000] f32, I[784*50000] f32, J[784*50000] f32,
//         inds1[100*2] i32, inds2[100*2] i32
// Output: 200 f32 (dgm1 flat [100] then dgm2 flat [100])

#define P_DIM   50000
#define W_IMG   28
#define N_OUT   200
#define SPLIT   4
#define CHUNK   (P_DIM / SPLIT)     // 12500
#define CHUNK4  (CHUNK / 4)         // 3125 float4 per chunk
#define NTHREADS 256
#define NBLOCKS (N_OUT * SPLIT)     // 800

__device__ float g_partial[N_OUT * SPLIT];
__device__ unsigned int g_done = 0;   // reset to 0 by the last block each call

__global__ __launch_bounds__(NTHREADS)
void fused_gathered_dot(const float* __restrict__ p,
                        const float* __restrict__ I,
                        const float* __restrict__ J,
                        const int*   __restrict__ inds1,
                        const int*   __restrict__ inds2,
                        float*       __restrict__ out) {
    int b = blockIdx.x;          // 0 .. 799
    int o = b >> 2;              // output index 0..199
    int c = b & (SPLIT - 1);     // K-chunk 0..3

    const float* mat;
    const int*   inds;
    int j;
    if (o < 100) { mat = I; inds = inds1; j = o; }
    else         { mat = J; inds = inds2; j = o - 100; }

    int r  = inds[2 * j + 0];
    int cc = inds[2 * j + 1];
    const float* row = mat + (size_t)(r * W_IMG + cc) * P_DIM + c * CHUNK;
    const float* pp  = p + c * CHUNK;

    const float4* row4 = reinterpret_cast<const float4*>(row);
    const float4* p4   = reinterpret_cast<const float4*>(pp);

    float sum = 0.0f;
    #pragma unroll 4
    for (int i = threadIdx.x; i < CHUNK4; i += NTHREADS) {
        float4 a = row4[i];
        float4 q = p4[i];
        sum += a.x * q.x + a.y * q.y + a.z * q.z + a.w * q.w;
    }

    // intra-block reduction
    #pragma unroll
    for (int off = 16; off > 0; off >>= 1)
        sum += __shfl_down_sync(0xffffffffu, sum, off);

    __shared__ float ws[NTHREADS / 32];
    __shared__ bool  s_last;
    if ((threadIdx.x & 31) == 0) ws[threadIdx.x >> 5] = sum;
    __syncthreads();

    if (threadIdx.x < (NTHREADS / 32)) {
        float v = ws[threadIdx.x];
        #pragma unroll
        for (int off = (NTHREADS / 64); off > 0; off >>= 1)
            v += __shfl_down_sync(0xffu, v, off);
        if (threadIdx.x == 0) g_partial[o * SPLIT + c] = v;
    }

    // signal completion; last block does the final 800 -> 200 reduce
    if (threadIdx.x == 0) {
        __threadfence();
        unsigned int prev = atomicAdd(&g_done, 1u);
        s_last = (prev == NBLOCKS - 1);
    }
    __syncthreads();

    if (s_last) {
        int oo = threadIdx.x;
        if (oo < N_OUT) {
            float s = 0.0f;
            #pragma unroll
            for (int k = 0; k < SPLIT; k++) s += g_partial[oo * SPLIT + k];
            out[oo] = s;
        }
        if (threadIdx.x == 0) g_done = 0;   // reset for next graph replay
    }
}

extern "C" void kernel_launch(void* const* d_in, const int* in_sizes, int n_in,
                              void* d_out, int out_size) {
    const float* p     = (const float*)d_in[0];
    const float* I     = (const float*)d_in[1];
    const float* J     = (const float*)d_in[2];
    const int*   inds1 = (const int*)d_in[3];
    const int*   inds2 = (const int*)d_in[4];
    float* out = (float*)d_out;

    fused_gathered_dot<<<NBLOCKS, NTHREADS>>>(p, I, J, inds1, inds2, out);
}